// round 1
// baseline (speedup 1.0000x reference)
#include <cuda_runtime.h>

#define N_NODES 50000
#define N_EDGES 800000
#define DIM 128
#define NLAYERS 3

// Scratch (no allocations allowed -> __device__ globals)
__device__ float g_h[N_NODES * DIM];
__device__ float g_agg[N_NODES * DIM];
__device__ int   g_deg[N_NODES];
__device__ int   g_off[N_NODES + 1];
__device__ int   g_cur[N_NODES];
__device__ int   g_srcs[N_EDGES];

// ---------------------------------------------------------------------------
// CSR construction: histogram -> scan -> fill
// ---------------------------------------------------------------------------
__global__ void zero_deg_kernel() {
    int i = blockIdx.x * blockDim.x + threadIdx.x;
    if (i < N_NODES) g_deg[i] = 0;
}

__global__ void hist_kernel(const int* __restrict__ dst) {
    int e = blockIdx.x * blockDim.x + threadIdx.x;
    if (e < N_EDGES) atomicAdd(&g_deg[dst[e]], 1);
}

// Single-block exclusive scan over 50000 degrees (Hillis-Steele per 1024 chunk)
__global__ void scan_kernel() {
    __shared__ int sh[1024];
    __shared__ int carry;
    if (threadIdx.x == 0) carry = 0;
    __syncthreads();
    for (int base = 0; base < N_NODES; base += 1024) {
        int i = base + threadIdx.x;
        int v = (i < N_NODES) ? g_deg[i] : 0;
        sh[threadIdx.x] = v;
        __syncthreads();
        for (int off = 1; off < 1024; off <<= 1) {
            int t = (threadIdx.x >= off) ? sh[threadIdx.x - off] : 0;
            __syncthreads();
            sh[threadIdx.x] += t;
            __syncthreads();
        }
        int excl = sh[threadIdx.x] - v;
        if (i < N_NODES) {
            int o = carry + excl;
            g_off[i] = o;
            g_cur[i] = o;
        }
        __syncthreads();
        if (threadIdx.x == 0) carry += sh[1023];
        __syncthreads();
    }
    if (threadIdx.x == 0) g_off[N_NODES] = carry;
}

__global__ void fill_kernel(const int* __restrict__ src, const int* __restrict__ dst) {
    int e = blockIdx.x * blockDim.x + threadIdx.x;
    if (e < N_EDGES) {
        int d = dst[e];
        int pos = atomicAdd(&g_cur[d], 1);
        g_srcs[pos] = src[e];
    }
}

// ---------------------------------------------------------------------------
// Aggregate: one warp per node, gather+sum its in-neighbor rows (no atomics)
// ---------------------------------------------------------------------------
__global__ __launch_bounds__(256) void aggregate_kernel() {
    int warp = (blockIdx.x * blockDim.x + threadIdx.x) >> 5;
    int lane = threadIdx.x & 31;
    if (warp >= N_NODES) return;
    int s = g_off[warp];
    int e = g_off[warp + 1];
    const float4* __restrict__ h4 = reinterpret_cast<const float4*>(g_h);
    float4 acc = make_float4(0.f, 0.f, 0.f, 0.f);
    for (int i = s; i < e; i++) {
        int src = g_srcs[i];
        float4 v = h4[src * 32 + lane];
        acc.x += v.x; acc.y += v.y; acc.z += v.z; acc.w += v.w;
    }
    reinterpret_cast<float4*>(g_agg)[warp * 32 + lane] = acc;
}

// ---------------------------------------------------------------------------
// GEMM: out[32rows x 128cols] per block.
//   FUSED=false: out = A @ W1 + bias                     (in_fc)
//   FUSED=true : out = relu(A @ W1 + B @ W2 + bias) + B  (GraphConv layer)
// Thread layout: 256 threads; lane (tid&31) -> 4-col group; warp (tid>>5) -> 4 rows.
// ---------------------------------------------------------------------------
template <bool FUSED>
__global__ __launch_bounds__(256) void gemm_kernel(
    const float* __restrict__ A, const float* __restrict__ W1,
    const float* __restrict__ B, const float* __restrict__ W2,
    const float* __restrict__ bias, float* __restrict__ out)
{
    __shared__ float sA[32][DIM];
    __shared__ float sB[FUSED ? 32 : 1][DIM];

    int tid = threadIdx.x;
    int row0 = blockIdx.x * 32;

    const float4* __restrict__ A4 = reinterpret_cast<const float4*>(A);
    const float4* __restrict__ B4 = reinterpret_cast<const float4*>(B);

#pragma unroll
    for (int i = 0; i < 4; i++) {
        int idx = tid + i * 256;      // 0..1023 over 32 rows x 32 float4
        int r = idx >> 5;
        int c = idx & 31;
        int gr = row0 + r;
        float4 va = (gr < N_NODES) ? A4[gr * 32 + c] : make_float4(0.f, 0.f, 0.f, 0.f);
        *reinterpret_cast<float4*>(&sA[r][c * 4]) = va;
        if (FUSED) {
            float4 vb = (gr < N_NODES) ? B4[gr * 32 + c] : make_float4(0.f, 0.f, 0.f, 0.f);
            *reinterpret_cast<float4*>(&sB[r][c * 4]) = vb;
        }
    }
    __syncthreads();

    int cg = tid & 31;   // column group: cols [4cg, 4cg+3]
    int rg = tid >> 5;   // row group:    rows [4rg, 4rg+3]

    float4 bv = *reinterpret_cast<const float4*>(&bias[cg * 4]);
    float4 acc[4];
#pragma unroll
    for (int r = 0; r < 4; r++) acc[r] = bv;

    const float4* __restrict__ W14 = reinterpret_cast<const float4*>(W1);
    const float4* __restrict__ W24 = reinterpret_cast<const float4*>(W2);

#pragma unroll 4
    for (int k = 0; k < DIM; k++) {
        float4 w1 = W14[k * 32 + cg];
#pragma unroll
        for (int r = 0; r < 4; r++) {
            float a = sA[rg * 4 + r][k];
            acc[r].x = fmaf(a, w1.x, acc[r].x);
            acc[r].y = fmaf(a, w1.y, acc[r].y);
            acc[r].z = fmaf(a, w1.z, acc[r].z);
            acc[r].w = fmaf(a, w1.w, acc[r].w);
        }
        if (FUSED) {
            float4 w2 = W24[k * 32 + cg];
#pragma unroll
            for (int r = 0; r < 4; r++) {
                float b = sB[rg * 4 + r][k];
                acc[r].x = fmaf(b, w2.x, acc[r].x);
                acc[r].y = fmaf(b, w2.y, acc[r].y);
                acc[r].z = fmaf(b, w2.z, acc[r].z);
                acc[r].w = fmaf(b, w2.w, acc[r].w);
            }
        }
    }

#pragma unroll
    for (int r = 0; r < 4; r++) {
        int gr = row0 + rg * 4 + r;
        if (gr < N_NODES) {
            float4 v = acc[r];
            if (FUSED) {
                v.x = fmaxf(v.x, 0.f);
                v.y = fmaxf(v.y, 0.f);
                v.z = fmaxf(v.z, 0.f);
                v.w = fmaxf(v.w, 0.f);
                float4 res = *reinterpret_cast<const float4*>(&sB[rg * 4 + r][cg * 4]);
                v.x += res.x; v.y += res.y; v.z += res.z; v.w += res.w;
            }
            reinterpret_cast<float4*>(out)[gr * 32 + cg] = v;
        }
    }
}

// ---------------------------------------------------------------------------
// Launch
// ---------------------------------------------------------------------------
extern "C" void kernel_launch(void* const* d_in, const int* in_sizes, int n_in,
                              void* d_out, int out_size)
{
    const float* x       = (const float*)d_in[0];
    const int*   ei      = (const int*)  d_in[1];
    const float* in_fc_w = (const float*)d_in[2];
    const float* in_fc_b = (const float*)d_in[3];
    const float* w_rel   = (const float*)d_in[4];
    const float* b_rel   = (const float*)d_in[5];
    const float* w_root  = (const float*)d_in[6];
    float* out = (float*)d_out;

    const int* src = ei;
    const int* dst = ei + N_EDGES;

    float* h_ptr;   cudaGetSymbolAddress((void**)&h_ptr, g_h);
    float* agg_ptr; cudaGetSymbolAddress((void**)&agg_ptr, g_agg);

    const int GEMM_BLOCKS = (N_NODES + 31) / 32;   // 1563
    const int EDGE_BLOCKS = (N_EDGES + 255) / 256; // 3125
    const int NODE_BLOCKS = (N_NODES + 255) / 256; // 196
    const int AGG_BLOCKS  = (N_NODES * 32 + 255) / 256; // 1 warp per node

    // CSR build (per call; deterministic work)
    zero_deg_kernel<<<NODE_BLOCKS, 256>>>();
    hist_kernel<<<EDGE_BLOCKS, 256>>>(dst);
    scan_kernel<<<1, 1024>>>();
    fill_kernel<<<EDGE_BLOCKS, 256>>>(src, dst);

    // in_fc: h = x @ in_fc_w + b
    gemm_kernel<false><<<GEMM_BLOCKS, 256>>>(x, in_fc_w, nullptr, nullptr, in_fc_b, h_ptr);

    // 3 GraphConv layers
    for (int l = 0; l < NLAYERS; l++) {
        aggregate_kernel<<<AGG_BLOCKS, 256>>>();
        float* dst_buf = (l == NLAYERS - 1) ? out : h_ptr;
        gemm_kernel<true><<<GEMM_BLOCKS, 256>>>(
            agg_ptr, w_rel + l * DIM * DIM,
            h_ptr,   w_root + l * DIM * DIM,
            b_rel + l * DIM, dst_buf);
    }
}

// round 3
// speedup vs baseline: 2.2074x; 2.2074x over previous
#include <cuda_runtime.h>
#include <cuda_bf16.h>
#include <mma.h>
#include <cstdint>

using namespace nvcuda;

#define N_NODES 50000
#define N_EDGES 800000
#define DIM 128
#define NLAYERS 3
#define NBLK_NODE 196   // ceil(50000/256)

// ---------------------------------------------------------------------------
// Scratch (no allocations allowed -> __device__ globals)
// ---------------------------------------------------------------------------
__device__ float g_h[N_NODES * DIM];
__device__ float g_agg[N_NODES * DIM];
__device__ int   g_deg[N_NODES];
__device__ int   g_off[N_NODES + 1];
__device__ int   g_cur[N_NODES];
__device__ int   g_srcs[N_EDGES];
__device__ int   g_bsum[256];
__device__ int   g_bbase[256];

// ---------------------------------------------------------------------------
// bf16 hi/lo split of a pair of floats, packed as bf16x2 words
// ---------------------------------------------------------------------------
__device__ __forceinline__ void split2(float a0, float a1, uint32_t& hi, uint32_t& lo) {
    __nv_bfloat16 h0 = __float2bfloat16(a0);
    __nv_bfloat16 h1 = __float2bfloat16(a1);
    float r0 = a0 - __bfloat162float(h0);
    float r1 = a1 - __bfloat162float(h1);
    __nv_bfloat16 l0 = __float2bfloat16(r0);
    __nv_bfloat16 l1 = __float2bfloat16(r1);
    hi = (uint32_t)__bfloat16_as_ushort(h0) | ((uint32_t)__bfloat16_as_ushort(h1) << 16);
    lo = (uint32_t)__bfloat16_as_ushort(l0) | ((uint32_t)__bfloat16_as_ushort(l1) << 16);
}

// ---------------------------------------------------------------------------
// WMMA bf16x3 GEMM (HMMA path; tcgen05 not available under compute_103 target)
//   FUSED=false: out = A1 @ W1 + bias                       (K=128)
//   FUSED=true : out = relu([A1|A2] @ [W1;W2] + bias) + A2  (K=256, resid=A2 rows)
// CTA: 128 rows x 128 cols. 8 warps as 4(m) x 2(n); warp tile 32x64.
// K chunked by 32 through shared memory (fp32 -> bf16 hi/lo split on the fly).
// ---------------------------------------------------------------------------
#define A_HI 0
#define A_LO 10240
#define W_HI 20480
#define W_LO 29184
#define SMEM_BYTES 37888   // also reused as 8 warps x 16x68 fp32 epilogue scratch (34816 B)

template <bool FUSED>
__global__ __launch_bounds__(256) void gemm_wmma_kernel(
    const float* __restrict__ A1, const float* __restrict__ W1,
    const float* __restrict__ A2, const float* __restrict__ W2,
    const float* __restrict__ bias, float* __restrict__ out)
{
    __shared__ __align__(16) char smem_raw[SMEM_BYTES];

    const int tid  = threadIdx.x;
    const int wid  = tid >> 5;
    const int lane = tid & 31;
    const int wm   = wid & 3;     // warp row block (32 rows)
    const int wn   = wid >> 2;    // warp col block (64 cols)
    const int row0 = blockIdx.x * 128;

    constexpr int KCAT   = FUSED ? 256 : 128;
    constexpr int NCHUNK = KCAT / 32;

    wmma::fragment<wmma::accumulator, 16, 16, 16, float> acc[2][4];
#pragma unroll
    for (int mi = 0; mi < 2; mi++)
#pragma unroll
        for (int ni = 0; ni < 4; ni++)
            wmma::fill_fragment(acc[mi][ni], 0.0f);

    for (int kc = 0; kc < NCHUNK; kc++) {
        const int k0 = kc * 32;
        __syncthreads();

        // --- stage A chunk: rows [row0,row0+128) x cols [k0,k0+32) of A_cat ---
#pragma unroll
        for (int t = 0; t < 4; t++) {
            int q  = tid + t * 256;          // 0..1023 over 128 rows x 8 float4
            int r  = q >> 3;
            int c4 = q & 7;
            int col = k0 + c4 * 4;
            int gr  = row0 + r;
            float4 v = make_float4(0.f, 0.f, 0.f, 0.f);
            if (gr < N_NODES) {
                const float* base = (!FUSED || col < 128) ? A1 : A2;
                int cc = (!FUSED || col < 128) ? col : col - 128;
                v = *reinterpret_cast<const float4*>(base + (size_t)gr * DIM + cc);
            }
            uint32_t h0, l0, h1, l1;
            split2(v.x, v.y, h0, l0);
            split2(v.z, v.w, h1, l1);
            uint32_t boff = (uint32_t)r * 80u + (uint32_t)c4 * 8u;   // ldm 40 bf16
            *reinterpret_cast<uint2*>(smem_raw + A_HI + boff) = make_uint2(h0, h1);
            *reinterpret_cast<uint2*>(smem_raw + A_LO + boff) = make_uint2(l0, l1);
        }

        // --- stage W chunk: rows [k0,k0+32) of W_cat x all 128 cols ---
#pragma unroll
        for (int t = 0; t < 4; t++) {
            int q  = tid + t * 256;          // 0..1023 over 32 rows x 32 float4
            int kk = q >> 5;
            int c4 = q & 31;
            int krow = k0 + kk;
            const float* base = (!FUSED || krow < 128) ? W1 : W2;
            int kr = (!FUSED || krow < 128) ? krow : krow - 128;
            float4 v = *reinterpret_cast<const float4*>(base + (size_t)kr * DIM + c4 * 4);
            uint32_t h0, l0, h1, l1;
            split2(v.x, v.y, h0, l0);
            split2(v.z, v.w, h1, l1);
            uint32_t boff = (uint32_t)kk * 272u + (uint32_t)c4 * 8u;  // ldm 136 bf16
            *reinterpret_cast<uint2*>(smem_raw + W_HI + boff) = make_uint2(h0, h1);
            *reinterpret_cast<uint2*>(smem_raw + W_LO + boff) = make_uint2(l0, l1);
        }
        __syncthreads();

        // --- MMA: 2 k-steps of 16 ---
#pragma unroll
        for (int ks = 0; ks < 2; ks++) {
            wmma::fragment<wmma::matrix_a, 16, 16, 16, __nv_bfloat16, wmma::row_major> ah[2], al[2];
#pragma unroll
            for (int mi = 0; mi < 2; mi++) {
                const __nv_bfloat16* pa_hi = reinterpret_cast<const __nv_bfloat16*>(smem_raw + A_HI)
                                           + (wm * 32 + mi * 16) * 40 + ks * 16;
                const __nv_bfloat16* pa_lo = reinterpret_cast<const __nv_bfloat16*>(smem_raw + A_LO)
                                           + (wm * 32 + mi * 16) * 40 + ks * 16;
                wmma::load_matrix_sync(ah[mi], pa_hi, 40);
                wmma::load_matrix_sync(al[mi], pa_lo, 40);
            }
#pragma unroll
            for (int ni = 0; ni < 4; ni++) {
                wmma::fragment<wmma::matrix_b, 16, 16, 16, __nv_bfloat16, wmma::row_major> bh, bl;
                const __nv_bfloat16* pb_hi = reinterpret_cast<const __nv_bfloat16*>(smem_raw + W_HI)
                                           + (ks * 16) * 136 + wn * 64 + ni * 16;
                const __nv_bfloat16* pb_lo = reinterpret_cast<const __nv_bfloat16*>(smem_raw + W_LO)
                                           + (ks * 16) * 136 + wn * 64 + ni * 16;
                wmma::load_matrix_sync(bh, pb_hi, 136);
                wmma::load_matrix_sync(bl, pb_lo, 136);
#pragma unroll
                for (int mi = 0; mi < 2; mi++) {
                    wmma::mma_sync(acc[mi][ni], ah[mi], bh, acc[mi][ni]);
                    wmma::mma_sync(acc[mi][ni], ah[mi], bl, acc[mi][ni]);
                    wmma::mma_sync(acc[mi][ni], al[mi], bh, acc[mi][ni]);
                }
            }
        }
    }

    // --- epilogue: per-warp 16x68 fp32 scratch, fuse bias/relu/residual ---
    __syncthreads();
    float* sc = reinterpret_cast<float*>(smem_raw) + wid * (16 * 68);
    const int col0 = wn * 64;
    const int rl   = lane >> 1;
    const int half = lane & 1;

#pragma unroll
    for (int mi = 0; mi < 2; mi++) {
#pragma unroll
        for (int ni = 0; ni < 4; ni++)
            wmma::store_matrix_sync(sc + ni * 16, acc[mi][ni], 68, wmma::mem_row_major);
        __syncwarp();

        int grow = row0 + wm * 32 + mi * 16 + rl;
        if (grow < N_NODES) {
#pragma unroll
            for (int j = 0; j < 8; j++) {
                int c = half * 32 + j * 4;
                float4 v = *reinterpret_cast<const float4*>(sc + rl * 68 + c);
                float4 b4 = *reinterpret_cast<const float4*>(bias + col0 + c);
                v.x += b4.x; v.y += b4.y; v.z += b4.z; v.w += b4.w;
                if (FUSED) {
                    v.x = fmaxf(v.x, 0.f); v.y = fmaxf(v.y, 0.f);
                    v.z = fmaxf(v.z, 0.f); v.w = fmaxf(v.w, 0.f);
                    float4 rr = *reinterpret_cast<const float4*>(A2 + (size_t)grow * DIM + col0 + c);
                    v.x += rr.x; v.y += rr.y; v.z += rr.z; v.w += rr.w;
                }
                *reinterpret_cast<float4*>(out + (size_t)grow * DIM + col0 + c) = v;
            }
        }
        __syncwarp();
    }
}

// ---------------------------------------------------------------------------
// CSR construction: histogram -> hierarchical scan -> fill
// ---------------------------------------------------------------------------
__global__ void zero_deg_kernel() {
    int i = blockIdx.x * blockDim.x + threadIdx.x;
    if (i < N_NODES) g_deg[i] = 0;
}

__global__ void hist_kernel(const int* __restrict__ dst) {
    int e = blockIdx.x * blockDim.x + threadIdx.x;
    if (e < N_EDGES) atomicAdd(&g_deg[dst[e]], 1);
}

__global__ void block_reduce_kernel() {
    __shared__ int sh[256];
    int tid = threadIdx.x;
    int i = blockIdx.x * 256 + tid;
    int v = (i < N_NODES) ? g_deg[i] : 0;
    sh[tid] = v;
    __syncthreads();
#pragma unroll
    for (int s = 128; s > 0; s >>= 1) {
        if (tid < s) sh[tid] += sh[tid + s];
        __syncthreads();
    }
    if (tid == 0) g_bsum[blockIdx.x] = sh[0];
}

__global__ void scan_bsum_kernel() {
    __shared__ int sh[256];
    int tid = threadIdx.x;
    int v = (tid < NBLK_NODE) ? g_bsum[tid] : 0;
    sh[tid] = v;
    __syncthreads();
#pragma unroll
    for (int off = 1; off < 256; off <<= 1) {
        int t = (tid >= off) ? sh[tid - off] : 0;
        __syncthreads();
        sh[tid] += t;
        __syncthreads();
    }
    if (tid < NBLK_NODE) g_bbase[tid] = sh[tid] - v;  // exclusive
    if (tid == 0) g_off[N_NODES] = N_EDGES;
}

__global__ void scan_write_kernel() {
    __shared__ int sh[256];
    int tid = threadIdx.x;
    int i = blockIdx.x * 256 + tid;
    int v = (i < N_NODES) ? g_deg[i] : 0;
    sh[tid] = v;
    __syncthreads();
#pragma unroll
    for (int off = 1; off < 256; off <<= 1) {
        int t = (tid >= off) ? sh[tid - off] : 0;
        __syncthreads();
        sh[tid] += t;
        __syncthreads();
    }
    if (i < N_NODES) {
        int o = g_bbase[blockIdx.x] + sh[tid] - v;
        g_off[i] = o;
        g_cur[i] = o;
    }
}

__global__ void fill_kernel(const int* __restrict__ src, const int* __restrict__ dst) {
    int e = blockIdx.x * blockDim.x + threadIdx.x;
    if (e < N_EDGES) {
        int d = dst[e];
        int pos = atomicAdd(&g_cur[d], 1);
        g_srcs[pos] = src[e];
    }
}

// ---------------------------------------------------------------------------
// Aggregate: one warp per node, gather+sum its in-neighbor rows (no atomics)
// ---------------------------------------------------------------------------
__global__ __launch_bounds__(256) void aggregate_kernel() {
    int warp = (blockIdx.x * blockDim.x + threadIdx.x) >> 5;
    int lane = threadIdx.x & 31;
    if (warp >= N_NODES) return;
    int s = g_off[warp];
    int e = g_off[warp + 1];
    const float4* __restrict__ h4 = reinterpret_cast<const float4*>(g_h);
    float4 acc = make_float4(0.f, 0.f, 0.f, 0.f);
    for (int i = s; i < e; i++) {
        int src = g_srcs[i];
        float4 v = h4[(size_t)src * 32 + lane];
        acc.x += v.x; acc.y += v.y; acc.z += v.z; acc.w += v.w;
    }
    reinterpret_cast<float4*>(g_agg)[(size_t)warp * 32 + lane] = acc;
}

// ---------------------------------------------------------------------------
// Launch
// ---------------------------------------------------------------------------
extern "C" void kernel_launch(void* const* d_in, const int* in_sizes, int n_in,
                              void* d_out, int out_size)
{
    const float* x       = (const float*)d_in[0];
    const int*   ei      = (const int*)  d_in[1];
    const float* in_fc_w = (const float*)d_in[2];
    const float* in_fc_b = (const float*)d_in[3];
    const float* w_rel   = (const float*)d_in[4];
    const float* b_rel   = (const float*)d_in[5];
    const float* w_root  = (const float*)d_in[6];
    float* out = (float*)d_out;

    const int* src = ei;
    const int* dst = ei + N_EDGES;

    float* h_ptr;   cudaGetSymbolAddress((void**)&h_ptr, g_h);
    float* agg_ptr; cudaGetSymbolAddress((void**)&agg_ptr, g_agg);

    const int GEMM_BLOCKS = (N_NODES + 127) / 128;       // 391
    const int EDGE_BLOCKS = (N_EDGES + 255) / 256;       // 3125
    const int AGG_BLOCKS  = (N_NODES * 32 + 255) / 256;  // 1 warp per node

    // CSR build
    zero_deg_kernel<<<NBLK_NODE, 256>>>();
    hist_kernel<<<EDGE_BLOCKS, 256>>>(dst);
    block_reduce_kernel<<<NBLK_NODE, 256>>>();
    scan_bsum_kernel<<<1, 256>>>();
    scan_write_kernel<<<NBLK_NODE, 256>>>();
    fill_kernel<<<EDGE_BLOCKS, 256>>>(src, dst);

    // in_fc: h = x @ in_fc_w + b
    gemm_wmma_kernel<false><<<GEMM_BLOCKS, 256>>>(
        x, in_fc_w, nullptr, nullptr, in_fc_b, h_ptr);

    // 3 GraphConv layers: out = relu(agg@w_rel + h@w_root + b) + h
    for (int l = 0; l < NLAYERS; l++) {
        aggregate_kernel<<<AGG_BLOCKS, 256>>>();
        float* dst_buf = (l == NLAYERS - 1) ? out : h_ptr;
        gemm_wmma_kernel<true><<<GEMM_BLOCKS, 256>>>(
            agg_ptr, w_rel + (size_t)l * DIM * DIM,
            h_ptr,   w_root + (size_t)l * DIM * DIM,
            b_rel + (size_t)l * DIM, dst_buf);
    }
}